// round 8
// baseline (speedup 1.0000x reference)
#include <cuda_runtime.h>
#include <cstdint>

#define PI_F 3.14159265358979323846f

constexpr int HW      = 81;
constexpr int NG      = 4;
constexpr long long NX = 512LL * 512LL * 81LL;   // 21,233,664 elements of x
constexpr int N4      = (int)(NX / 4);            // 5,308,416 float4 chunks
constexpr int THREADS = 256;
constexpr int BLOCKS  = 2592;                     // 81*32: stride divisible by 81
constexpr int TOTAL_T = BLOCKS * THREADS;         // 663,552
constexpr int ITERS   = N4 / TOTAL_T;             // 8 exactly

// Precomputed 4x81 Gabor table (1.3 KB), built once per launch by a tiny kernel.
__device__ float g_filt[NG * HW];

__global__ void build_filters(const float* __restrict__ theta,
                              const float* __restrict__ lam)
{
    int i = threadIdx.x;
    if (i >= NG * HW) return;
    int g  = i / HW;
    int hw = i % HW;
    float fy = (float)(hw / 9) - 4.0f;   // ys = arange(9) - 4
    float fx = (float)(hw % 9) - 4.0f;   // xs = arange(9) - 4
    float th = theta[g];
    float l  = lam[g];
    float s, c;
    sincosf(th, &s, &c);
    float xr = fx * c + fy * s;
    float yr = -fx * s + fy * c;
    float env = expf(-(xr * xr + yr * yr) * (0.5f / (PI_F * PI_F))); // sigma = pi
    g_filt[i] = env * cosf(2.0f * PI_F * xr * l);
}

// x load: read-only path + L2 evict_last cache-hint policy so x (85MB) stays
// resident in L2 (126MB) across graph replays while the write stream
// (evict_first) passes through. Policy route works at 128-bit width (the bare
// .L2::evict_last ld modifier requires 256-bit on this ptxas).
__device__ __forceinline__ float4 ldg_evict_last(const float4* p, uint64_t pol)
{
    float4 v;
    asm volatile("ld.global.nc.L2::cache_hint.v4.f32 {%0,%1,%2,%3}, [%4], %5;"
                 : "=f"(v.x), "=f"(v.y), "=f"(v.z), "=f"(v.w)
                 : "l"(p), "l"(pol));
    return v;
}

__global__ __launch_bounds__(THREADS)
void gabor_mul_kernel(const float* __restrict__ x,
                      float* __restrict__ out)
{
    // Cheap prologue: 16 scalar loads from the 1.3KB resident table.
    // Iteration stride TOTAL_T*4 = 2,654,208 elements is divisible by 81,
    // so each lane's hw phase is invariant across all 8 iterations.
    int t0  = blockIdx.x * THREADS + threadIdx.x;
    int hw0 = (t0 * 4) % HW;

    uint64_t pol;
    asm("createpolicy.fractional.L2::evict_last.b64 %0, 1.0;" : "=l"(pol));

    float f[NG][4];
#pragma unroll
    for (int g = 0; g < NG; g++) {
        int h = hw0;
#pragma unroll
        for (int k = 0; k < 4; k++) {
            f[g][k] = g_filt[g * HW + h];
            h++;
            if (h == HW) h = 0;
        }
    }

    const float4* __restrict__ x4 = (const float4*)x;
    float4* __restrict__ og[NG];
#pragma unroll
    for (int g = 0; g < NG; g++) og[g] = (float4*)(out + (size_t)g * NX);

    // MLP=8: all eight independent LDG.128 front-batched (evict_last policy),
    // then 32 streaming STG.128 (evict_first).
    float4 v[ITERS];
#pragma unroll
    for (int j = 0; j < ITERS; j++)
        v[j] = ldg_evict_last(&x4[t0 + j * TOTAL_T], pol);

#pragma unroll
    for (int j = 0; j < ITERS; j++) {
        int idx = t0 + j * TOTAL_T;
#pragma unroll
        for (int g = 0; g < NG; g++) {
            float4 o;
            o.x = f[g][0] * v[j].x;
            o.y = f[g][1] * v[j].y;
            o.z = f[g][2] * v[j].z;
            o.w = f[g][3] * v[j].w;
            __stcs(&og[g][idx], o);
        }
    }
}

extern "C" void kernel_launch(void* const* d_in, const int* in_sizes, int n_in,
                              void* d_out, int out_size)
{
    const float* x     = (const float*)d_in[0];
    const float* theta = (const float*)d_in[1];
    const float* lam   = (const float*)d_in[2];
    float* out         = (float*)d_out;

    build_filters<<<1, NG * HW>>>(theta, lam);
    gabor_mul_kernel<<<BLOCKS, THREADS>>>(x, out);
}

// round 12
// speedup vs baseline: 1.0089x; 1.0089x over previous
#include <cuda_runtime.h>

#define PI_F 3.14159265358979323846f

constexpr int HW      = 81;
constexpr int NG      = 4;
constexpr long long NX = 512LL * 512LL * 81LL;   // 21,233,664 elements of x
constexpr int N4      = (int)(NX / 4);            // 5,308,416 float4 chunks
constexpr int THREADS = 256;
constexpr int BLOCKS  = 2592;                     // 81*32: stride divisible by 81
constexpr int TOTAL_T = BLOCKS * THREADS;         // 663,552
constexpr int ITERS   = N4 / TOTAL_T;             // 8 exactly
constexpr int PF      = 4;                        // prefetch distance

// Precomputed 4x81 Gabor table (1.3 KB), built once per launch by a tiny kernel.
__device__ float g_filt[NG * HW];

__global__ void build_filters(const float* __restrict__ theta,
                              const float* __restrict__ lam)
{
    int i = threadIdx.x;
    if (i >= NG * HW) return;
    int g  = i / HW;
    int hw = i % HW;
    float fy = (float)(hw / 9) - 4.0f;   // ys = arange(9) - 4
    float fx = (float)(hw % 9) - 4.0f;   // xs = arange(9) - 4
    float th = theta[g];
    float l  = lam[g];
    float s, c;
    sincosf(th, &s, &c);
    float xr = fx * c + fy * s;
    float yr = -fx * s + fy * c;
    float env = expf(-(xr * xr + yr * yr) * (0.5f / (PI_F * PI_F))); // sigma = pi
    g_filt[i] = env * cosf(2.0f * PI_F * xr * l);
}

__global__ __launch_bounds__(THREADS)
void gabor_mul_kernel(const float* __restrict__ x,
                      float* __restrict__ out)
{
    // Cheap prologue: 16 scalar loads from the 1.3KB resident table.
    // Iteration stride TOTAL_T*4 = 2,654,208 elements is divisible by 81,
    // so each lane's hw phase is invariant across all 8 iterations.
    int t0  = blockIdx.x * THREADS + threadIdx.x;
    int hw0 = (t0 * 4) % HW;

    float f[NG][4];
#pragma unroll
    for (int g = 0; g < NG; g++) {
        int h = hw0;
#pragma unroll
        for (int k = 0; k < 4; k++) {
            f[g][k] = g_filt[g * HW + h];
            h++;
            if (h == HW) h = 0;
        }
    }

    const float4* __restrict__ x4 = (const float4*)x;
    float4* __restrict__ og[NG];
#pragma unroll
    for (int g = 0; g < NG; g++) og[g] = (float4*)(out + (size_t)g * NX);

    // Software pipeline, prefetch distance 4: each warp keeps ~4 LDG.128 in
    // flight CONTINUOUSLY (vs batch-8-then-drain), raising time-averaged
    // outstanding loads. Loads evict-normal (x stays L2-warm across replays);
    // stores evict-first so the 340MB write stream doesn't evict x.
    float4 buf[PF];
#pragma unroll
    for (int j = 0; j < PF; j++)
        buf[j] = x4[t0 + j * TOTAL_T];

#pragma unroll
    for (int j = 0; j < ITERS; j++) {
        float4 v = buf[j % PF];
        if (j + PF < ITERS)
            buf[j % PF] = x4[t0 + (j + PF) * TOTAL_T];   // issue before stores

        int idx = t0 + j * TOTAL_T;
#pragma unroll
        for (int g = 0; g < NG; g++) {
            float4 o;
            o.x = f[g][0] * v.x;
            o.y = f[g][1] * v.y;
            o.z = f[g][2] * v.z;
            o.w = f[g][3] * v.w;
            __stcs(&og[g][idx], o);
        }
    }
}

extern "C" void kernel_launch(void* const* d_in, const int* in_sizes, int n_in,
                              void* d_out, int out_size)
{
    const float* x     = (const float*)d_in[0];
    const float* theta = (const float*)d_in[1];
    const float* lam   = (const float*)d_in[2];
    float* out         = (float*)d_out;

    build_filters<<<1, NG * HW>>>(theta, lam);
    gabor_mul_kernel<<<BLOCKS, THREADS>>>(x, out);
}

// round 15
// speedup vs baseline: 1.0098x; 1.0009x over previous
#include <cuda_runtime.h>
#include <cstdint>

#define PI_F 3.14159265358979323846f

constexpr int HW      = 81;
constexpr int NG      = 4;
constexpr long long NX = 512LL * 512LL * 81LL;   // 21,233,664 elements of x
constexpr int N8      = (int)(NX / 8);            // 2,654,208 float8 chunks
constexpr int THREADS = 256;
constexpr int BLOCKS  = 2592;                     // 81*32
constexpr int TOTAL_T = BLOCKS * THREADS;         // 663,552
constexpr int ITERS   = N8 / TOTAL_T;             // 4 exactly
// per-iteration element span = TOTAL_T*8 = 5,308,416 = 81 * 65,536  (phase-invariant)
constexpr int PF      = 2;                        // prefetch distance

// Precomputed 4x81 Gabor table (1.3 KB), built once per launch by a tiny kernel.
__device__ float g_filt[NG * HW];

__global__ void build_filters(const float* __restrict__ theta,
                              const float* __restrict__ lam)
{
    int i = threadIdx.x;
    if (i >= NG * HW) return;
    int g  = i / HW;
    int hw = i % HW;
    float fy = (float)(hw / 9) - 4.0f;   // ys = arange(9) - 4
    float fx = (float)(hw % 9) - 4.0f;   // xs = arange(9) - 4
    float th = theta[g];
    float l  = lam[g];
    float s, c;
    sincosf(th, &s, &c);
    float xr = fx * c + fy * s;
    float yr = -fx * s + fy * c;
    float env = expf(-(xr * xr + yr * yr) * (0.5f / (PI_F * PI_F))); // sigma = pi
    g_filt[i] = env * cosf(2.0f * PI_F * xr * l);
}

// 256-bit global load (read-only, evict-normal): 1KB contiguous per warp.
__device__ __forceinline__ void ldg256(const uint32_t* p, uint32_t v[8])
{
    asm volatile("ld.global.nc.v8.b32 {%0,%1,%2,%3,%4,%5,%6,%7}, [%8];"
                 : "=r"(v[0]), "=r"(v[1]), "=r"(v[2]), "=r"(v[3]),
                   "=r"(v[4]), "=r"(v[5]), "=r"(v[6]), "=r"(v[7])
                 : "l"(p));
}

// 256-bit streaming store (L2 evict-first): long same-row DRAM bursts,
// and the write stream doesn't displace x in L2.
__device__ __forceinline__ void stg256(uint32_t* p, const uint32_t v[8])
{
    asm volatile("st.global.L2::evict_first.v8.b32 [%0], {%1,%2,%3,%4,%5,%6,%7,%8};"
                 :: "l"(p),
                    "r"(v[0]), "r"(v[1]), "r"(v[2]), "r"(v[3]),
                    "r"(v[4]), "r"(v[5]), "r"(v[6]), "r"(v[7])
                 : "memory");
}

__global__ __launch_bounds__(THREADS)
void gabor_mul_kernel(const float* __restrict__ x,
                      float* __restrict__ out)
{
    // Each thread owns 8 consecutive floats per iteration. Iteration span is
    // divisible by 81, so the 8 filter phases per lane are loop-invariant.
    int t0  = blockIdx.x * THREADS + threadIdx.x;
    int hw0 = (t0 * 8) % HW;

    float f[NG][8];
#pragma unroll
    for (int g = 0; g < NG; g++) {
        int h = hw0;
#pragma unroll
        for (int k = 0; k < 8; k++) {
            f[g][k] = g_filt[g * HW + h];
            h++;
            if (h == HW) h = 0;
        }
    }

    const uint32_t* __restrict__ xb = (const uint32_t*)x;
    uint32_t* __restrict__ og[NG];
#pragma unroll
    for (int g = 0; g < NG; g++) og[g] = (uint32_t*)(out + (size_t)g * NX);

    // PF=2 pipeline over 4 iterations: ~2 LDG.256 continuously in flight per
    // thread while 256-bit stores drain.
    uint32_t buf[PF][8];
#pragma unroll
    for (int j = 0; j < PF; j++)
        ldg256(xb + (size_t)(t0 + j * TOTAL_T) * 8, buf[j]);

#pragma unroll
    for (int j = 0; j < ITERS; j++) {
        uint32_t v[8];
#pragma unroll
        for (int k = 0; k < 8; k++) v[k] = buf[j % PF][k];

        if (j + PF < ITERS)
            ldg256(xb + (size_t)(t0 + (j + PF) * TOTAL_T) * 8, buf[j % PF]);

        size_t idx8 = (size_t)(t0 + j * TOTAL_T) * 8;
#pragma unroll
        for (int g = 0; g < NG; g++) {
            uint32_t o[8];
#pragma unroll
            for (int k = 0; k < 8; k++)
                o[k] = __float_as_uint(f[g][k] * __uint_as_float(v[k]));
            stg256(og[g] + idx8, o);
        }
    }
}

extern "C" void kernel_launch(void* const* d_in, const int* in_sizes, int n_in,
                              void* d_out, int out_size)
{
    const float* x     = (const float*)d_in[0];
    const float* theta = (const float*)d_in[1];
    const float* lam   = (const float*)d_in[2];
    float* out         = (float*)d_out;

    build_filters<<<1, NG * HW>>>(theta, lam);
    gabor_mul_kernel<<<BLOCKS, THREADS>>>(x, out);
}